// round 15
// baseline (speedup 1.0000x reference)
#include <cuda_runtime.h>
#include <cuda_fp16.h>
#include <cstdint>
#include <cstddef>

// Problem constants
#define DIAGNUM 50000
#define MEDNUM  20000
#define PRONUM  40000
#define FEATDIM 128
#define N1 (DIAGNUM + MEDNUM)   // 70000
#define N2 (PRONUM + MEDNUM)    // 60000
#define NNZ1 1120000
#define NNZ2 960000
#define CAP 64                  // Poisson(16): P(deg>64) ~ 1e-21 (clamped anyway)

#define NCNT (2 * N1 + 2 * N2)  // 260000 counters

// g_cnt is zero-initialized at module load; thereafter each gather task resets
// the counters it consumed, so every launch starts from zero without a
// dedicated zeroing kernel.
__device__ int  g_cnt[NCNT];
__device__ int2 g_bkt1[(size_t)2 * N1 * CAP];      // graph1: lists 0,1
__device__ int2 g_bkt2[(size_t)2 * N2 * CAP];      // graph2: lists 0,1

// fp16 concatenated embedding tables
__device__ __half g_e1[(size_t)N1 * FEATDIM];      // [dEmbed | mEmbed] 17.9 MB
__device__ __half g_e2[(size_t)N2 * FEATDIM];      // [pEmbed | mEmbed] 15.4 MB

// ---------------------------------------------------------------------------
// Fused bucket + convert. Blocks [0, BUCKET_BLOCKS) do edge bucketing
// (atomic-latency-bound); remaining blocks do fp32->fp16 table conversion
// (bandwidth-bound). Co-resident on SMs => overlapped.
// ---------------------------------------------------------------------------
#define BUCKET_THREADS 256
#define BUCKET_BLOCKS ((NNZ1 + NNZ2 + BUCKET_THREADS - 1) / BUCKET_THREADS)   // 8125
#define CONV_TOTAL ((N1 + N2) * FEATDIM / 4)                                  // 4,160,000
#define CONV_BLOCKS ((CONV_TOTAL + BUCKET_THREADS - 1) / BUCKET_THREADS)      // 16250

__global__ void prep_kernel(const int* __restrict__ r1, const int* __restrict__ c1,
                            const float* __restrict__ v1,
                            const int* __restrict__ r2, const int* __restrict__ c2,
                            const float* __restrict__ v2,
                            int2* __restrict__ bkt1, int2* __restrict__ bkt2,
                            const float4* __restrict__ dE,
                            const float4* __restrict__ mE,
                            const float4* __restrict__ pE) {
    if (blockIdx.x < BUCKET_BLOCKS) {
        int tid = blockIdx.x * blockDim.x + threadIdx.x;
        if (tid < NNZ1) {                           // graph1 pair at e = 2*tid
            int e = 2 * tid;
            int list = (e >= NNZ1) ? 1 : 0;
            int2   r = __ldg(reinterpret_cast<const int2*>(r1) + tid);
            int2   c = __ldg(reinterpret_cast<const int2*>(c1) + tid);
            float2 v = __ldg(reinterpret_cast<const float2*>(v1) + tid);
            int base0 = list * N1 + r.x;
            int base1 = list * N1 + r.y;
            int s0 = atomicAdd(&g_cnt[base0], 1);
            int s1 = atomicAdd(&g_cnt[base1], 1);
            if (s0 < CAP) bkt1[(size_t)base0 * CAP + s0] = make_int2(c.x, __float_as_int(v.x));
            if (s1 < CAP) bkt1[(size_t)base1 * CAP + s1] = make_int2(c.y, __float_as_int(v.y));
        } else {                                    // graph2 pair
            int p = tid - NNZ1;
            if (p >= NNZ2) return;
            int e = 2 * p;
            int list = (e >= NNZ2) ? 1 : 0;
            int2   r = __ldg(reinterpret_cast<const int2*>(r2) + p);
            int2   c = __ldg(reinterpret_cast<const int2*>(c2) + p);
            float2 v = __ldg(reinterpret_cast<const float2*>(v2) + p);
            int base0 = list * N2 + r.x;
            int base1 = list * N2 + r.y;
            int s0 = atomicAdd(&g_cnt[2 * N1 + base0], 1);
            int s1 = atomicAdd(&g_cnt[2 * N1 + base1], 1);
            if (s0 < CAP) bkt2[(size_t)base0 * CAP + s0] = make_int2(c.x, __float_as_int(v.x));
            if (s1 < CAP) bkt2[(size_t)base1 * CAP + s1] = make_int2(c.y, __float_as_int(v.y));
        }
    } else {
        const int q1 = N1 * FEATDIM / 4;
        const int q2 = N2 * FEATDIM / 4;
        const int qd = DIAGNUM * FEATDIM / 4;
        const int qp = PRONUM * FEATDIM / 4;
        int i = (blockIdx.x - BUCKET_BLOCKS) * blockDim.x + threadIdx.x;
        if (i < q1) {
            float4 x = (i < qd) ? __ldg(dE + i) : __ldg(mE + (i - qd));
            __half2 lo = __floats2half2_rn(x.x, x.y);
            __half2 hi = __floats2half2_rn(x.z, x.w);
            uint2 packed;
            packed.x = *reinterpret_cast<unsigned*>(&lo);
            packed.y = *reinterpret_cast<unsigned*>(&hi);
            reinterpret_cast<uint2*>(g_e1)[i] = packed;
        } else {
            int j = i - q1;
            if (j >= q2) return;
            float4 x = (j < qp) ? __ldg(pE + j) : __ldg(mE + (j - qp));
            __half2 lo = __floats2half2_rn(x.x, x.y);
            __half2 hi = __floats2half2_rn(x.z, x.w);
            uint2 packed;
            packed.x = *reinterpret_cast<unsigned*>(&lo);
            packed.y = *reinterpret_cast<unsigned*>(&hi);
            reinterpret_cast<uint2*>(g_e2)[j] = packed;
        }
    }
}

// ---------------------------------------------------------------------------
// Core: accumulate one list-pair (half-warp per list), relu both, cross-half
// add. Padded iterations load UNCONDITIONALLY from clamped slot 0 (same hot
// line every time — near-zero extra traffic; conditional 128-bit loads
// generate BSSY branch regions and serialize, per R14 measurement).
// Lane 0 resets the pair's counters after reading (self-cleaning; exact
// once-per-counter coverage across tasks, so no zeroing kernel needed).
// ---------------------------------------------------------------------------
__device__ __forceinline__ void pair_core(const int2* __restrict__ bktArr,
                                          int b0, int b1, int cntBase,
                                          const uint4* __restrict__ tbl,
                                          int lane, int half, int hlane,
                                          float acc[8]) {
    int n0 = min(g_cnt[cntBase + b0], CAP);
    int n1 = min(g_cnt[cntBase + b1], CAP);
    if (lane == 0) {
        g_cnt[cntBase + b0] = 0;
        g_cnt[cntBase + b1] = 0;
    }
    int nmax = max(n0, n1);
    int nmy  = half ? n1 : n0;
    const int2* myBkt = bktArr + (size_t)(half ? b1 : b0) * CAP;

    #pragma unroll
    for (int i = 0; i < 8; i++) acc[i] = 0.f;

    for (int k = 0; k < nmax; k += 4) {
        int2 e[4];
        #pragma unroll
        for (int j = 0; j < 4; j++) {
            int kk = k + j;
            int idx = (kk < nmy) ? kk : 0;      // clamp (slot 0 always valid)
            e[j] = __ldg(myBkt + idx);
        }
        uint4 x[4];
        float v[4];
        #pragma unroll
        for (int j = 0; j < 4; j++) {
            v[j] = (k + j < nmy) ? __int_as_float(e[j].y) : 0.f;
            x[j] = __ldg(tbl + (size_t)e[j].x * 16 + hlane);   // unconditional
        }
        #pragma unroll
        for (int j = 0; j < 4; j++) {
            float2 f0 = __half22float2(*reinterpret_cast<__half2*>(&x[j].x));
            float2 f1 = __half22float2(*reinterpret_cast<__half2*>(&x[j].y));
            float2 f2 = __half22float2(*reinterpret_cast<__half2*>(&x[j].z));
            float2 f3 = __half22float2(*reinterpret_cast<__half2*>(&x[j].w));
            acc[0] = fmaf(v[j], f0.x, acc[0]);
            acc[1] = fmaf(v[j], f0.y, acc[1]);
            acc[2] = fmaf(v[j], f1.x, acc[2]);
            acc[3] = fmaf(v[j], f1.y, acc[3]);
            acc[4] = fmaf(v[j], f2.x, acc[4]);
            acc[5] = fmaf(v[j], f2.y, acc[5]);
            acc[6] = fmaf(v[j], f3.x, acc[6]);
            acc[7] = fmaf(v[j], f3.y, acc[7]);
        }
    }

    #pragma unroll
    for (int i = 0; i < 8; i++) acc[i] = fmaxf(acc[i], 0.f);
    #pragma unroll
    for (int i = 0; i < 8; i++) acc[i] += __shfl_xor_sync(0xffffffffu, acc[i], 16);
}

// ---------------------------------------------------------------------------
// Gather: one warp per TASK; m-tasks (2x work) first (LPT). Plain stores only.
// ---------------------------------------------------------------------------
#define NTASKS 110000

__global__ void __launch_bounds__(256) gather_kernel(const float* __restrict__ inter,
                                                     float4* __restrict__ out) {
    int task = (blockIdx.x * blockDim.x + threadIdx.x) >> 5;
    int lane = threadIdx.x & 31;
    if (task >= NTASKS) return;
    int half  = lane >> 4;
    int hlane = lane & 15;

    float res8[8];
    int outRow;

    if (task < MEDNUM) {                        // m-row: both graphs, blend
        int m = task;
        float a1[8], a2[8];
        pair_core(g_bkt1, DIAGNUM + m, N1 + DIAGNUM + m, 0,
                  reinterpret_cast<const uint4*>(g_e1), lane, half, hlane, a1);
        pair_core(g_bkt2, PRONUM + m, N2 + PRONUM + m, 2 * N1,
                  reinterpret_cast<const uint4*>(g_e2), lane, half, hlane, a2);
        float t = __ldg(inter);
        float u = 1.f - t;
        #pragma unroll
        for (int i = 0; i < 8; i++) res8[i] = t * a1[i] + u * a2[i];
        outRow = m;
    } else if (task < MEDNUM + DIAGNUM) {       // d-row, graph1
        int r = task - MEDNUM;
        pair_core(g_bkt1, r, N1 + r, 0,
                  reinterpret_cast<const uint4*>(g_e1), lane, half, hlane, res8);
        outRow = MEDNUM + r;
    } else {                                    // p-row, graph2
        int r = task - MEDNUM - DIAGNUM;
        pair_core(g_bkt2, r, N2 + r, 2 * N1,
                  reinterpret_cast<const uint4*>(g_e2), lane, half, hlane, res8);
        outRow = MEDNUM + DIAGNUM + r;
    }

    float4 res = half ? make_float4(res8[4], res8[5], res8[6], res8[7])
                      : make_float4(res8[0], res8[1], res8[2], res8[3]);
    res.x *= 2.f; res.y *= 2.f; res.z *= 2.f; res.w *= 2.f;
    out[(size_t)outRow * 32 + 2 * hlane + half] = res;
}

// ---------------------------------------------------------------------------
extern "C" void kernel_launch(void* const* d_in, const int* in_sizes, int n_in,
                              void* d_out, int out_size) {
    const int*   a1r = (const int*)d_in[0];
    const int*   a1c = (const int*)d_in[1];
    const float* a1v = (const float*)d_in[2];
    const int*   a2r = (const int*)d_in[3];
    const int*   a2c = (const int*)d_in[4];
    const float* a2v = (const float*)d_in[5];
    const float4* dE = (const float4*)d_in[6];
    const float4* mE = (const float4*)d_in[7];
    const float4* pE = (const float4*)d_in[8];
    const float* inter = (const float*)d_in[9];
    float4* out = (float4*)d_out;

    int2* bkt1;  cudaGetSymbolAddress((void**)&bkt1, g_bkt1);
    int2* bkt2;  cudaGetSymbolAddress((void**)&bkt2, g_bkt2);

    // 1. Fused bucket + fp16 conversion (counters zero at entry: static init
    //    on first launch, self-cleaned by gather on every launch)
    prep_kernel<<<BUCKET_BLOCKS + CONV_BLOCKS, BUCKET_THREADS>>>(
        a1r, a1c, a1v, a2r, a2c, a2v, bkt1, bkt2, dE, mE, pE);

    // 2. Gather: m-tasks first (2x work), then d/p
    {
        int threads = 256;
        int blocks = (NTASKS * 32 + threads - 1) / threads;
        gather_kernel<<<blocks, threads>>>(inter, out);
    }
}

// round 16
// speedup vs baseline: 2.8845x; 2.8845x over previous
#include <cuda_runtime.h>
#include <cuda_fp16.h>
#include <cstdint>
#include <cstddef>

// Problem constants
#define DIAGNUM 50000
#define MEDNUM  20000
#define PRONUM  40000
#define FEATDIM 128
#define N1 (DIAGNUM + MEDNUM)   // 70000
#define N2 (PRONUM + MEDNUM)    // 60000
#define NNZ1 1120000
#define NNZ2 960000
#define CAP 64                  // Poisson(16): P(deg>64) ~ 1e-21 (clamped anyway)

#define NCNT (2 * N1 + 2 * N2)  // 260000 counters

__device__ int  g_cnt[NCNT];
__device__ int2 g_bkt1[(size_t)2 * N1 * CAP];      // graph1: lists 0,1
__device__ int2 g_bkt2[(size_t)2 * N2 * CAP];      // graph2: lists 0,1

// fp16 concatenated embedding tables
__device__ __half g_e1[(size_t)N1 * FEATDIM];      // [dEmbed | mEmbed] 17.9 MB
__device__ __half g_e2[(size_t)N2 * FEATDIM];      // [pEmbed | mEmbed] 15.4 MB

// ---------------------------------------------------------------------------
// Zero counters (int4 grid-stride; 65000 stores)
// ---------------------------------------------------------------------------
__global__ void zero_cnt_kernel() {
    int4* p = reinterpret_cast<int4*>(g_cnt);
    int n4 = NCNT / 4;
    int stride = gridDim.x * blockDim.x;
    int4 z = make_int4(0, 0, 0, 0);
    for (int i = blockIdx.x * blockDim.x + threadIdx.x; i < n4; i += stride)
        p[i] = z;
}

// ---------------------------------------------------------------------------
// Fused bucket + convert. Blocks [0, BUCKET_BLOCKS) do edge bucketing
// (atomic-latency-bound); remaining blocks do fp32->fp16 table conversion
// (bandwidth-bound). Co-resident on SMs => overlapped.
// ---------------------------------------------------------------------------
#define BUCKET_THREADS 256
#define BUCKET_BLOCKS ((NNZ1 + NNZ2 + BUCKET_THREADS - 1) / BUCKET_THREADS)   // 8125
#define CONV_TOTAL ((N1 + N2) * FEATDIM / 4)                                  // 4,160,000
#define CONV_BLOCKS ((CONV_TOTAL + BUCKET_THREADS - 1) / BUCKET_THREADS)      // 16250

__global__ void prep_kernel(const int* __restrict__ r1, const int* __restrict__ c1,
                            const float* __restrict__ v1,
                            const int* __restrict__ r2, const int* __restrict__ c2,
                            const float* __restrict__ v2,
                            int2* __restrict__ bkt1, int2* __restrict__ bkt2,
                            const float4* __restrict__ dE,
                            const float4* __restrict__ mE,
                            const float4* __restrict__ pE) {
    if (blockIdx.x < BUCKET_BLOCKS) {
        // ------- bucket scatter: two edges per thread -------
        int tid = blockIdx.x * blockDim.x + threadIdx.x;
        if (tid < NNZ1) {                           // graph1 pair at e = 2*tid
            int e = 2 * tid;
            int list = (e >= NNZ1) ? 1 : 0;
            int2   r = __ldg(reinterpret_cast<const int2*>(r1) + tid);
            int2   c = __ldg(reinterpret_cast<const int2*>(c1) + tid);
            float2 v = __ldg(reinterpret_cast<const float2*>(v1) + tid);
            int base0 = list * N1 + r.x;
            int base1 = list * N1 + r.y;
            int s0 = atomicAdd(&g_cnt[base0], 1);
            int s1 = atomicAdd(&g_cnt[base1], 1);
            if (s0 < CAP) bkt1[(size_t)base0 * CAP + s0] = make_int2(c.x, __float_as_int(v.x));
            if (s1 < CAP) bkt1[(size_t)base1 * CAP + s1] = make_int2(c.y, __float_as_int(v.y));
        } else {                                    // graph2 pair
            int p = tid - NNZ1;
            if (p >= NNZ2) return;
            int e = 2 * p;
            int list = (e >= NNZ2) ? 1 : 0;
            int2   r = __ldg(reinterpret_cast<const int2*>(r2) + p);
            int2   c = __ldg(reinterpret_cast<const int2*>(c2) + p);
            float2 v = __ldg(reinterpret_cast<const float2*>(v2) + p);
            int base0 = list * N2 + r.x;
            int base1 = list * N2 + r.y;
            int s0 = atomicAdd(&g_cnt[2 * N1 + base0], 1);
            int s1 = atomicAdd(&g_cnt[2 * N1 + base1], 1);
            if (s0 < CAP) bkt2[(size_t)base0 * CAP + s0] = make_int2(c.x, __float_as_int(v.x));
            if (s1 < CAP) bkt2[(size_t)base1 * CAP + s1] = make_int2(c.y, __float_as_int(v.y));
        }
    } else {
        // ------- fp32 -> fp16 table conversion -------
        const int q1 = N1 * FEATDIM / 4;
        const int q2 = N2 * FEATDIM / 4;
        const int qd = DIAGNUM * FEATDIM / 4;
        const int qp = PRONUM * FEATDIM / 4;
        int i = (blockIdx.x - BUCKET_BLOCKS) * blockDim.x + threadIdx.x;
        if (i < q1) {
            float4 x = (i < qd) ? __ldg(dE + i) : __ldg(mE + (i - qd));
            __half2 lo = __floats2half2_rn(x.x, x.y);
            __half2 hi = __floats2half2_rn(x.z, x.w);
            uint2 packed;
            packed.x = *reinterpret_cast<unsigned*>(&lo);
            packed.y = *reinterpret_cast<unsigned*>(&hi);
            reinterpret_cast<uint2*>(g_e1)[i] = packed;
        } else {
            int j = i - q1;
            if (j >= q2) return;
            float4 x = (j < qp) ? __ldg(pE + j) : __ldg(mE + (j - qp));
            __half2 lo = __floats2half2_rn(x.x, x.y);
            __half2 hi = __floats2half2_rn(x.z, x.w);
            uint2 packed;
            packed.x = *reinterpret_cast<unsigned*>(&lo);
            packed.y = *reinterpret_cast<unsigned*>(&hi);
            reinterpret_cast<uint2*>(g_e2)[j] = packed;
        }
    }
}

// ---------------------------------------------------------------------------
// Core: accumulate one list-pair (half-warp per list), relu both, cross-half
// add => every lane holds g = relu(h0)+relu(h1) for its feature chunk.
// READ-ONLY except registers: no stores into shared-read structures (R15
// lesson: counter self-reset inside this kernel caused a 3.3x regression).
// Padded iterations load unconditionally from clamped slot 0 (hot line,
// near-zero extra traffic; conditional 128-bit loads cause BSSY serialization
// per R14 measurement).
// ---------------------------------------------------------------------------
__device__ __forceinline__ void pair_core(const int2* __restrict__ bktArr,
                                          int b0, int b1, int cntBase,
                                          const uint4* __restrict__ tbl,
                                          int half, int hlane, float acc[8]) {
    int n0 = min(g_cnt[cntBase + b0], CAP);
    int n1 = min(g_cnt[cntBase + b1], CAP);
    int nmax = max(n0, n1);
    int nmy  = half ? n1 : n0;
    const int2* myBkt = bktArr + (size_t)(half ? b1 : b0) * CAP;

    #pragma unroll
    for (int i = 0; i < 8; i++) acc[i] = 0.f;

    for (int k = 0; k < nmax; k += 4) {
        int2 e[4];
        #pragma unroll
        for (int j = 0; j < 4; j++) {
            int kk = k + j;
            int idx = (kk < nmy) ? kk : 0;      // clamp (slot 0 always valid)
            e[j] = __ldg(myBkt + idx);
        }
        uint4 x[4];
        float v[4];
        #pragma unroll
        for (int j = 0; j < 4; j++) {
            v[j] = (k + j < nmy) ? __int_as_float(e[j].y) : 0.f;
            x[j] = __ldg(tbl + (size_t)e[j].x * 16 + hlane);   // unconditional
        }
        #pragma unroll
        for (int j = 0; j < 4; j++) {
            float2 f0 = __half22float2(*reinterpret_cast<__half2*>(&x[j].x));
            float2 f1 = __half22float2(*reinterpret_cast<__half2*>(&x[j].y));
            float2 f2 = __half22float2(*reinterpret_cast<__half2*>(&x[j].z));
            float2 f3 = __half22float2(*reinterpret_cast<__half2*>(&x[j].w));
            acc[0] = fmaf(v[j], f0.x, acc[0]);
            acc[1] = fmaf(v[j], f0.y, acc[1]);
            acc[2] = fmaf(v[j], f1.x, acc[2]);
            acc[3] = fmaf(v[j], f1.y, acc[3]);
            acc[4] = fmaf(v[j], f2.x, acc[4]);
            acc[5] = fmaf(v[j], f2.y, acc[5]);
            acc[6] = fmaf(v[j], f3.x, acc[6]);
            acc[7] = fmaf(v[j], f3.y, acc[7]);
        }
    }

    #pragma unroll
    for (int i = 0; i < 8; i++) acc[i] = fmaxf(acc[i], 0.f);
    #pragma unroll
    for (int i = 0; i < 8; i++) acc[i] += __shfl_xor_sync(0xffffffffu, acc[i], 16);
}

// ---------------------------------------------------------------------------
// Gather: one warp per TASK; m-tasks (2x work) first (LPT). Plain stores only.
// ---------------------------------------------------------------------------
#define NTASKS 110000

__global__ void __launch_bounds__(256) gather_kernel(const float* __restrict__ inter,
                                                     float4* __restrict__ out) {
    int task = (blockIdx.x * blockDim.x + threadIdx.x) >> 5;
    int lane = threadIdx.x & 31;
    if (task >= NTASKS) return;
    int half  = lane >> 4;
    int hlane = lane & 15;

    float res8[8];
    int outRow;

    if (task < MEDNUM) {                        // m-row: both graphs, blend
        int m = task;
        float a1[8], a2[8];
        pair_core(g_bkt1, DIAGNUM + m, N1 + DIAGNUM + m, 0,
                  reinterpret_cast<const uint4*>(g_e1), half, hlane, a1);
        pair_core(g_bkt2, PRONUM + m, N2 + PRONUM + m, 2 * N1,
                  reinterpret_cast<const uint4*>(g_e2), half, hlane, a2);
        float t = __ldg(inter);
        float u = 1.f - t;
        #pragma unroll
        for (int i = 0; i < 8; i++) res8[i] = t * a1[i] + u * a2[i];
        outRow = m;
    } else if (task < MEDNUM + DIAGNUM) {       // d-row, graph1
        int r = task - MEDNUM;
        pair_core(g_bkt1, r, N1 + r, 0,
                  reinterpret_cast<const uint4*>(g_e1), half, hlane, res8);
        outRow = MEDNUM + r;
    } else {                                    // p-row, graph2
        int r = task - MEDNUM - DIAGNUM;
        pair_core(g_bkt2, r, N2 + r, 2 * N1,
                  reinterpret_cast<const uint4*>(g_e2), half, hlane, res8);
        outRow = MEDNUM + DIAGNUM + r;
    }

    float4 res = half ? make_float4(res8[4], res8[5], res8[6], res8[7])
                      : make_float4(res8[0], res8[1], res8[2], res8[3]);
    res.x *= 2.f; res.y *= 2.f; res.z *= 2.f; res.w *= 2.f;
    out[(size_t)outRow * 32 + 2 * hlane + half] = res;
}

// ---------------------------------------------------------------------------
extern "C" void kernel_launch(void* const* d_in, const int* in_sizes, int n_in,
                              void* d_out, int out_size) {
    const int*   a1r = (const int*)d_in[0];
    const int*   a1c = (const int*)d_in[1];
    const float* a1v = (const float*)d_in[2];
    const int*   a2r = (const int*)d_in[3];
    const int*   a2c = (const int*)d_in[4];
    const float* a2v = (const float*)d_in[5];
    const float4* dE = (const float4*)d_in[6];
    const float4* mE = (const float4*)d_in[7];
    const float4* pE = (const float4*)d_in[8];
    const float* inter = (const float*)d_in[9];
    float4* out = (float4*)d_out;

    int2* bkt1;  cudaGetSymbolAddress((void**)&bkt1, g_bkt1);
    int2* bkt2;  cudaGetSymbolAddress((void**)&bkt2, g_bkt2);

    // 1. Zero counters (tiny)
    zero_cnt_kernel<<<128, 256>>>();

    // 2. Fused bucket (first, longer) + fp16 conversion (fills remaining SMs)
    prep_kernel<<<BUCKET_BLOCKS + CONV_BLOCKS, BUCKET_THREADS>>>(
        a1r, a1c, a1v, a2r, a2c, a2v, bkt1, bkt2, dE, mE, pE);

    // 3. Gather: m-tasks first (2x work), then d/p; all plain stores
    {
        int threads = 256;
        int blocks = (NTASKS * 32 + threads - 1) / threads;
        gather_kernel<<<blocks, threads>>>(inter, out);
    }
}